// round 12
// baseline (speedup 1.0000x reference)
#include <cuda_runtime.h>
#include <math.h>

typedef unsigned long long ull;

__device__ __forceinline__ ull pack2(float lo, float hi) {
    ull r; asm("mov.b64 %0, {%1,%2};" : "=l"(r) : "f"(lo), "f"(hi)); return r;
}
__device__ __forceinline__ void unpack2(ull v, float& lo, float& hi) {
    asm("mov.b64 {%0,%1}, %2;" : "=f"(lo), "=f"(hi) : "l"(v));
}
__device__ __forceinline__ ull fma2(ull a, ull b, ull c) {
    ull d; asm("fma.rn.f32x2 %0, %1, %2, %3;" : "=l"(d) : "l"(a), "l"(b), "l"(c)); return d;
}
__device__ __forceinline__ ull add2(ull a, ull b) {
    ull d; asm("add.rn.f32x2 %0, %1, %2;" : "=l"(d) : "l"(a), "l"(b)); return d;
}

// Identity: alpha*cos(v) + beta*sin(v) = R*cos(v - phi),
//   R = sqrt(alpha^2+beta^2), phi = atan2(beta, alpha).
// R is folded into the smem weight table; per pixel the feature is
// one packed add (v - phi) + one __cosf.
//
// Block = 16 batch rows, 8 warps, each warp owns 2 full rows (392 float2
// pixel pairs). Weights pre-packed in smem:
// swp[kk][j] = float4(R0*w[2kk][p0], R0*w[2kk+1][p0], R1*w[2kk][p1], R1*w[2kk+1][p1])
// read as longlong2 -> two fma.rn.f32x2 operands.
__global__ __launch_bounds__(256, 4)
void quanv_fused(const float* __restrict__ x,
                 const float* __restrict__ params,
                 const float* __restrict__ w,
                 const float* __restrict__ bias,
                 float* __restrict__ out) {
    __shared__ float4 swp4[5 * 392];    // 31360 B
    __shared__ float  s_R[4], s_phi[4];

    const int tid = threadIdx.x;

    // ---- SU(2) observable coefficients -> (R, phi): 4 threads ----
    if (tid < 4) {
        const int c = tid;
        float u00r = 1.f, u00i = 0.f, u01r = 0.f, u01i = 0.f;
        float u10r = 0.f, u10i = 0.f, u11r = 1.f, u11i = 0.f;
        for (int d = 0; d < 4; d++) {
            float rz1 = params[(d * 4 + c) * 3 + 0];
            float ry  = params[(d * 4 + c) * 3 + 1];
            float rz2 = params[(d * 4 + c) * 3 + 2];
            {
                float sp, cp; __sincosf(0.5f * rz1, &sp, &cp);
                float ci = -sp, cr = cp, t_;
                t_ = u00r * cr - u00i * ci; u00i = u00r * ci + u00i * cr; u00r = t_;
                t_ = u01r * cr - u01i * ci; u01i = u01r * ci + u01i * cr; u01r = t_;
                t_ = u10r * cr + u10i * ci; u10i = -u10r * ci + u10i * cr; u10r = t_;
                t_ = u11r * cr + u11i * ci; u11i = -u11r * ci + u11i * cr; u11r = t_;
            }
            {
                float ss, cc; __sincosf(0.5f * ry, &ss, &cc);
                float n00r = cc * u00r - ss * u10r, n00i = cc * u00i - ss * u10i;
                float n01r = cc * u01r - ss * u11r, n01i = cc * u01i - ss * u11i;
                float n10r = ss * u00r + cc * u10r, n10i = ss * u00i + cc * u10i;
                float n11r = ss * u01r + cc * u11r, n11i = ss * u01i + cc * u11i;
                u00r = n00r; u00i = n00i; u01r = n01r; u01i = n01i;
                u10r = n10r; u10i = n10i; u11r = n11r; u11i = n11i;
            }
            {
                float sp, cp; __sincosf(0.5f * rz2, &sp, &cp);
                float ci = -sp, cr = cp, t_;
                t_ = u00r * cr - u00i * ci; u00i = u00r * ci + u00i * cr; u00r = t_;
                t_ = u01r * cr - u01i * ci; u01i = u01r * ci + u01i * cr; u01r = t_;
                t_ = u10r * cr + u10i * ci; u10i = -u10r * ci + u10i * cr; u10r = t_;
                t_ = u11r * cr + u11i * ci; u11i = -u11r * ci + u11i * cr; u11r = t_;
            }
        }
        float al = (u00r * u00r + u00i * u00i) - (u10r * u10r + u10i * u10i);
        float be = (u00r * u01r + u00i * u01i) - (u10r * u11r + u10i * u11i);
        s_R[c]   = sqrtf(al * al + be * be);
        s_phi[c] = atan2f(be, al);
    }
    __syncthreads();

    // ---- permuted weights * R: pair j -> pixels (2j, 2j+1), same image row ----
    for (int j = tid; j < 392; j += 256) {
        int p0 = 2 * j;
        int r = p0 / 28, c = p0 - r * 28;                          // c even
        int ch0 = (r & 1) << 1;                                    // col even
        int f0 = ((r >> 1) * 14 + (c >> 1)) * 4 + ch0;
        int f1 = f0 + 1;                                           // col odd
        float R0 = s_R[ch0], R1 = s_R[ch0 | 1];
#pragma unroll
        for (int kk = 0; kk < 5; kk++)
            swp4[kk * 392 + j] = make_float4(R0 * w[(2 * kk) * 784 + f0],
                                             R0 * w[(2 * kk + 1) * 784 + f0],
                                             R1 * w[(2 * kk) * 784 + f1],
                                             R1 * w[(2 * kk + 1) * 784 + f1]);
    }
    __syncthreads();

    const longlong2* swp = reinterpret_cast<const longlong2*>(swp4);

    // ---- main loop: warp owns rows (row0, row0+1), all 392 pairs ----
    const int warp = tid >> 5;
    const int lane = tid & 31;
    // packed -phi for (even col, odd col), by image-row parity
    const ull mphi[2] = { pack2(-s_phi[0], -s_phi[1]),
                          pack2(-s_phi[2], -s_phi[3]) };
    const size_t row0 = (size_t)blockIdx.x * 16 + warp * 2;
    const float2* xp2 = (const float2*)(x + row0 * 784);

    ull acc[2][5];
#pragma unroll
    for (int r = 0; r < 2; r++)
#pragma unroll
        for (int kk = 0; kk < 5; kk++) acc[r][kk] = 0ull;

    // prefetch iter 0
    float2 xv[2];
#pragma unroll
    for (int r = 0; r < 2; r++) xv[r] = __ldg(&xp2[r * 392 + lane]);

#pragma unroll 4
    for (int t = 0; t < 12; t++) {
        const int j = t * 32 + lane;
        float2 cur[2];
#pragma unroll
        for (int r = 0; r < 2; r++) cur[r] = xv[r];
        // prefetch next (t=11 prefetches the 8-lane tail, clamped)
        {
            int jn = j + 32;
            jn = (jn < 392) ? jn : 384;
#pragma unroll
            for (int r = 0; r < 2; r++) xv[r] = __ldg(&xp2[r * 392 + jn]);
        }

        int rowi = j / 14;                  // 14 pairs per image row
        ull mp = (rowi & 1) ? mphi[1] : mphi[0];

        ull fd0[2], fd1[2];
#pragma unroll
        for (int r = 0; r < 2; r++) {
            ull dv = add2(pack2(cur[r].x, cur[r].y), mp);
            float d0, d1;
            unpack2(dv, d0, d1);
            float f0 = __cosf(d0);
            float f1 = __cosf(d1);
            fd0[r] = pack2(f0, f0);
            fd1[r] = pack2(f1, f1);
        }
#pragma unroll
        for (int kk = 0; kk < 5; kk++) {
            longlong2 wv = swp[kk * 392 + j];   // LDS.128, conflict-free
#pragma unroll
            for (int r = 0; r < 2; r++)
                acc[r][kk] = fma2(fd1[r], (ull)wv.y,
                                  fma2(fd0[r], (ull)wv.x, acc[r][kk]));
        }
    }
    // tail: pairs 384..391, lanes 0..7 (image row 27 -> odd parity)
    {
        const bool valid = (lane < 8);
        const int j = 384 + (valid ? lane : 0);
        ull fd0[2], fd1[2];
#pragma unroll
        for (int r = 0; r < 2; r++) {
            ull dv = add2(pack2(xv[r].x, xv[r].y), mphi[1]);
            float d0, d1;
            unpack2(dv, d0, d1);
            float f0 = valid ? __cosf(d0) : 0.f;
            float f1 = valid ? __cosf(d1) : 0.f;
            fd0[r] = pack2(f0, f0);
            fd1[r] = pack2(f1, f1);
        }
#pragma unroll
        for (int kk = 0; kk < 5; kk++) {
            longlong2 wv = swp[kk * 392 + j];
#pragma unroll
            for (int r = 0; r < 2; r++)
                acc[r][kk] = fma2(fd1[r], (ull)wv.y,
                                  fma2(fd0[r], (ull)wv.x, acc[r][kk]));
        }
    }

    // ---- warp butterfly reduce (packed) ----
#pragma unroll
    for (int r = 0; r < 2; r++)
#pragma unroll
        for (int kk = 0; kk < 5; kk++) {
            ull v = acc[r][kk];
            v = add2(v, __shfl_xor_sync(0xFFFFFFFFu, v, 16));
            v = add2(v, __shfl_xor_sync(0xFFFFFFFFu, v, 8));
            v = add2(v, __shfl_xor_sync(0xFFFFFFFFu, v, 4));
            v = add2(v, __shfl_xor_sync(0xFFFFFFFFu, v, 2));
            v = add2(v, __shfl_xor_sync(0xFFFFFFFFu, v, 1));
            acc[r][kk] = v;
        }

    // ---- epilogue: lane 0 -> row0, lane 1 -> row0+1; log-softmax + store ----
    if (lane < 2) {
        const int r = lane;
        float l[10];
#pragma unroll
        for (int kk = 0; kk < 5; kk++) {
            float lo, hi;
            unpack2(acc[r][kk], lo, hi);
            l[2 * kk]     = lo + bias[2 * kk];
            l[2 * kk + 1] = hi + bias[2 * kk + 1];
        }
        float m = l[0];
#pragma unroll
        for (int k = 1; k < 10; k++) m = fmaxf(m, l[k]);
        float sum = 0.f;
#pragma unroll
        for (int k = 0; k < 10; k++) sum += __expf(l[k] - m);
        float lse = m + __logf(sum);
        float2* op = (float2*)(out + (row0 + r) * 10);
#pragma unroll
        for (int kk = 0; kk < 5; kk++)
            op[kk] = make_float2(l[2 * kk] - lse, l[2 * kk + 1] - lse);
    }
}

extern "C" void kernel_launch(void* const* d_in, const int* in_sizes, int n_in,
                              void* d_out, int out_size) {
    const float* x      = (const float*)d_in[0];   // (8192,1,28,28)
    const float* params = (const float*)d_in[1];   // (4,4,3)
    const float* w      = (const float*)d_in[2];   // (10,784)
    const float* bias   = (const float*)d_in[3];   // (10,)
    float* out          = (float*)d_out;           // (8192,10)

    quanv_fused<<<512, 256>>>(x, params, w, bias, out);
}